// round 1
// baseline (speedup 1.0000x reference)
#include <cuda_runtime.h>

#define Bv 4
#define Sv 1024
#define Hv 2048
#define Nv 16
#define Dv 128

// Scratch (device globals: allocation-free per harness rules)
__device__ __align__(16) float g_Q[(size_t)Bv * Nv * Sv * Dv];  // 33.5 MB
__device__ __align__(16) float g_K[(size_t)Bv * Sv * Dv];
__device__ __align__(16) float g_V[(size_t)Bv * Sv * Dv];

// ---------------------------------------------------------------------------
// Unified projection kernel.
// gridDim = (B*S/64, 18): y in [0,16) -> Q head y ; y==16 -> K ; y==17 -> V.
// Each CTA: 64 rows (over B*S) x 128 cols, reduce H=2048, BK=32.
// 256 threads, each computes a 4x8 register tile. Pure FFMA inner loop.
// ---------------------------------------------------------------------------
__global__ __launch_bounds__(256, 1) void proj_kernel(
    const float* __restrict__ hs,
    const float* __restrict__ Wq, const float* __restrict__ bq,
    const float* __restrict__ Wk, const float* __restrict__ bk,
    const float* __restrict__ Wv, const float* __restrict__ bv)
{
    __shared__ float As[64][36];     // 64 rows x 32 k (pad to 36 for f4 align)
    __shared__ float Ws[32][128];    // 32 k x 128 d

    const int tid = threadIdx.x;
    const int tx = tid & 15;
    const int ty = tid >> 4;
    const int y = blockIdx.y;
    const int row0 = blockIdx.x * 64;

    const float* W;
    const float* bias;
    if (y < Nv)       { W = Wq + (size_t)y * Hv * Dv; bias = bq + y * Dv; }
    else if (y == Nv) { W = Wk; bias = bk; }
    else              { W = Wv; bias = bv; }

    float acc[4][8];
#pragma unroll
    for (int i = 0; i < 4; i++)
#pragma unroll
        for (int j = 0; j < 8; j++) acc[i][j] = 0.f;

    for (int k0 = 0; k0 < Hv; k0 += 32) {
        // Load A tile: 64x32 floats = 512 float4, 2 per thread
#pragma unroll
        for (int i = 0; i < 2; i++) {
            int f = tid + 256 * i;
            int r = f >> 3;
            int c = (f & 7) * 4;
            *(float4*)&As[r][c] =
                *(const float4*)&hs[(size_t)(row0 + r) * Hv + k0 + c];
        }
        // Load W tile: 32x128 floats = 1024 float4, 4 per thread
#pragma unroll
        for (int i = 0; i < 4; i++) {
            int f = tid + 256 * i;
            int r = f >> 5;
            int c = (f & 31) * 4;
            *(float4*)&Ws[r][c] =
                *(const float4*)&W[(size_t)(k0 + r) * Dv + c];
        }
        __syncthreads();

#pragma unroll
        for (int kk = 0; kk < 32; kk++) {
            float aa[4];
#pragma unroll
            for (int i = 0; i < 4; i++) aa[i] = As[ty * 4 + i][kk];
            float4 b0 = *(float4*)&Ws[kk][tx * 8];
            float4 b1 = *(float4*)&Ws[kk][tx * 8 + 4];
            float bb[8] = {b0.x, b0.y, b0.z, b0.w, b1.x, b1.y, b1.z, b1.w};
#pragma unroll
            for (int i = 0; i < 4; i++)
#pragma unroll
                for (int j = 0; j < 8; j++)
                    acc[i][j] = fmaf(aa[i], bb[j], acc[i][j]);
        }
        __syncthreads();
    }

    float4 bb0 = *(const float4*)&bias[tx * 8];
    float4 bb1 = *(const float4*)&bias[tx * 8 + 4];
    float bsv[8] = {bb0.x, bb0.y, bb0.z, bb0.w, bb1.x, bb1.y, bb1.z, bb1.w};

#pragma unroll
    for (int i = 0; i < 4; i++) {
        int row = row0 + ty * 4 + i;   // global row over B*S
        float* op;
        size_t off;
        if (y < Nv) {
            int b = row >> 10;         // S = 1024
            int s = row & 1023;
            off = ((size_t)(b * Nv + y) * Sv + s) * Dv;
            op = g_Q;
        } else {
            off = (size_t)row * Dv;
            op = (y == Nv) ? g_K : g_V;
        }
        float4 o0 = make_float4(acc[i][0] + bsv[0], acc[i][1] + bsv[1],
                                acc[i][2] + bsv[2], acc[i][3] + bsv[3]);
        float4 o1 = make_float4(acc[i][4] + bsv[4], acc[i][5] + bsv[5],
                                acc[i][6] + bsv[6], acc[i][7] + bsv[7]);
        *(float4*)&op[off + tx * 8] = o0;
        *(float4*)&op[off + tx * 8 + 4] = o1;
    }
}

// ---------------------------------------------------------------------------
// fp32 flash attention. grid = (S/64, N, B), 256 threads.
// Per CTA: 64 queries, loop over 16 KV tiles of 64 keys, D=128.
// Online softmax; O accumulated in registers (4 rows x 8 cols per thread).
// Row r is owned by the 16-lane group ty = r/4 (shfl reductions stay in-warp).
// ---------------------------------------------------------------------------
#define QSTR 132   // 128 + 4 pad (float4-aligned, odd multiple of 4)
#define SSTR 68

__global__ __launch_bounds__(256, 1) void attn_kernel(float* __restrict__ out)
{
    extern __shared__ float sm[];
    float* Qs  = sm;                      // 64*132
    float* Ks  = Qs + 64 * QSTR;          // 64*132
    float* Vs  = Ks + 64 * QSTR;          // 64*132
    float* Ss  = Vs + 64 * QSTR;          // 64*68
    float* m_s = Ss + 64 * SSTR;          // 64
    float* l_s = m_s + 64;                // 64

    const int tid = threadIdx.x;
    const int tx = tid & 15;
    const int ty = tid >> 4;
    const int qt = blockIdx.x;
    const int n  = blockIdx.y;
    const int b  = blockIdx.z;

    const float* Qg = g_Q + ((size_t)(b * Nv + n) * Sv + qt * 64) * Dv;
    const float* Kg = g_K + (size_t)b * Sv * Dv;
    const float* Vg = g_V + (size_t)b * Sv * Dv;

    // Load Q tile: 64x128 = 2048 float4, 8 per thread
#pragma unroll
    for (int i = 0; i < 8; i++) {
        int f = tid + 256 * i;
        int r = f >> 5;
        int c = (f & 31) * 4;
        *(float4*)&Qs[r * QSTR + c] = *(const float4*)&Qg[(size_t)r * Dv + c];
    }
    if (tid < 64) { m_s[tid] = -3.0e38f; l_s[tid] = 0.f; }

    float o[4][8];
#pragma unroll
    for (int i = 0; i < 4; i++)
#pragma unroll
        for (int j = 0; j < 8; j++) o[i][j] = 0.f;

    for (int t = 0; t < Sv / 64; t++) {
        __syncthreads();   // prev PV done (Ss/Vs safe) + Q/m_s visible at t=0
        const float* Kt = Kg + (size_t)t * 64 * Dv;
        const float* Vt = Vg + (size_t)t * 64 * Dv;
#pragma unroll
        for (int i = 0; i < 8; i++) {
            int f = tid + 256 * i;
            int r = f >> 5;
            int c = (f & 31) * 4;
            *(float4*)&Ks[r * QSTR + c] = *(const float4*)&Kt[(size_t)r * Dv + c];
            *(float4*)&Vs[r * QSTR + c] = *(const float4*)&Vt[(size_t)r * Dv + c];
        }
        __syncthreads();

        // Scores: rows ty*4+i, cols tx + 16*j (stride-16 cols -> conflict-free Ks reads)
        float s[4][4];
#pragma unroll
        for (int i = 0; i < 4; i++)
#pragma unroll
            for (int j = 0; j < 4; j++) s[i][j] = 0.f;

#pragma unroll 8
        for (int d = 0; d < Dv; d += 4) {
            float4 qa[4], kb[4];
#pragma unroll
            for (int i = 0; i < 4; i++)
                qa[i] = *(float4*)&Qs[(ty * 4 + i) * QSTR + d];
#pragma unroll
            for (int j = 0; j < 4; j++)
                kb[j] = *(float4*)&Ks[(tx + j * 16) * QSTR + d];
#pragma unroll
            for (int i = 0; i < 4; i++)
#pragma unroll
                for (int j = 0; j < 4; j++) {
                    s[i][j] = fmaf(qa[i].x, kb[j].x, s[i][j]);
                    s[i][j] = fmaf(qa[i].y, kb[j].y, s[i][j]);
                    s[i][j] = fmaf(qa[i].z, kb[j].z, s[i][j]);
                    s[i][j] = fmaf(qa[i].w, kb[j].w, s[i][j]);
                }
        }

        // Online softmax per row (16-lane shfl group = half-warp)
#pragma unroll
        for (int i = 0; i < 4; i++) {
            int row = ty * 4 + i;
            float tm = fmaxf(fmaxf(s[i][0], s[i][1]), fmaxf(s[i][2], s[i][3]));
#pragma unroll
            for (int off = 8; off >= 1; off >>= 1)
                tm = fmaxf(tm, __shfl_xor_sync(0xffffffffu, tm, off));
            float m_old = m_s[row];
            float m_new = fmaxf(m_old, tm);
            float ci = __expf(m_old - m_new);
            float p0 = __expf(s[i][0] - m_new);
            float p1 = __expf(s[i][1] - m_new);
            float p2 = __expf(s[i][2] - m_new);
            float p3 = __expf(s[i][3] - m_new);
            float rs = (p0 + p1) + (p2 + p3);
#pragma unroll
            for (int off = 8; off >= 1; off >>= 1)
                rs += __shfl_xor_sync(0xffffffffu, rs, off);
            if (tx == 0) {
                m_s[row] = m_new;
                l_s[row] = l_s[row] * ci + rs;
            }
            Ss[row * SSTR + 0 * 16 + tx] = p0;
            Ss[row * SSTR + 1 * 16 + tx] = p1;
            Ss[row * SSTR + 2 * 16 + tx] = p2;
            Ss[row * SSTR + 3 * 16 + tx] = p3;
#pragma unroll
            for (int jj = 0; jj < 8; jj++) o[i][jj] *= ci;
        }
        __syncthreads();

        // O += P @ V   (O cols = tx*8 .. tx*8+7)
#pragma unroll 4
        for (int kk = 0; kk < 64; kk++) {
            float pv[4];
#pragma unroll
            for (int i = 0; i < 4; i++) pv[i] = Ss[(ty * 4 + i) * SSTR + kk];
            float4 v0 = *(float4*)&Vs[kk * QSTR + tx * 8];
            float4 v1 = *(float4*)&Vs[kk * QSTR + tx * 8 + 4];
#pragma unroll
            for (int i = 0; i < 4; i++) {
                o[i][0] = fmaf(pv[i], v0.x, o[i][0]);
                o[i][1] = fmaf(pv[i], v0.y, o[i][1]);
                o[i][2] = fmaf(pv[i], v0.z, o[i][2]);
                o[i][3] = fmaf(pv[i], v0.w, o[i][3]);
                o[i][4] = fmaf(pv[i], v1.x, o[i][4]);
                o[i][5] = fmaf(pv[i], v1.y, o[i][5]);
                o[i][6] = fmaf(pv[i], v1.z, o[i][6]);
                o[i][7] = fmaf(pv[i], v1.w, o[i][7]);
            }
        }
    }
    __syncthreads();

#pragma unroll
    for (int i = 0; i < 4; i++) {
        int row = ty * 4 + i;
        float inv = 1.0f / l_s[row];
        size_t base = ((size_t)(b * Nv + n) * Sv + qt * 64 + row) * Dv;
        float4 o0 = make_float4(o[i][0] * inv, o[i][1] * inv,
                                o[i][2] * inv, o[i][3] * inv);
        float4 o1 = make_float4(o[i][4] * inv, o[i][5] * inv,
                                o[i][6] * inv, o[i][7] * inv);
        *(float4*)&out[base + tx * 8] = o0;
        *(float4*)&out[base + tx * 8 + 4] = o1;
    }
}

// ---------------------------------------------------------------------------
extern "C" void kernel_launch(void* const* d_in, const int* in_sizes, int n_in,
                              void* d_out, int out_size)
{
    const float* hs = (const float*)d_in[0];
    const float* Wq = (const float*)d_in[1];
    const float* bq = (const float*)d_in[2];
    const float* Wk = (const float*)d_in[3];
    const float* bk = (const float*)d_in[4];
    const float* Wv = (const float*)d_in[5];
    const float* bv = (const float*)d_in[6];
    float* out = (float*)d_out;

    dim3 gp((Bv * Sv) / 64, Nv + 2);
    proj_kernel<<<gp, 256>>>(hs, Wq, bq, Wk, bk, Wv, bv);

    const int smem_bytes = (64 * QSTR * 3 + 64 * SSTR + 128) * (int)sizeof(float);
    cudaFuncSetAttribute(attn_kernel,
                         cudaFuncAttributeMaxDynamicSharedMemorySize, smem_bytes);
    dim3 ga(Sv / 64, Nv, Bv);
    attn_kernel<<<ga, 256, smem_bytes>>>(out);
}

// round 3
// speedup vs baseline: 1.7334x; 1.7334x over previous
#include <cuda_runtime.h>
#include <cuda_bf16.h>
#include <cstdint>

#define Bv 4
#define Sv 1024
#define Hv 2048
#define Nv 16
#define Dv 128
#define NCOL 2304          // 18 * 128 fused output columns (16 Q heads, K, V)

// ---------------- device scratch (static: allocation-free) ------------------
__device__ __align__(16) float g_Q[(size_t)Bv * Nv * Sv * Dv];  // 33.5 MB
__device__ __align__(16) float g_K[(size_t)Bv * Sv * Dv];
__device__ __align__(16) float g_V[(size_t)Bv * Sv * Dv];
__device__ __align__(16) unsigned short g_Ahi[(size_t)Bv * Sv * Hv];
__device__ __align__(16) unsigned short g_Alo[(size_t)Bv * Sv * Hv];
__device__ __align__(16) unsigned short g_Bhi[(size_t)NCOL * Hv];
__device__ __align__(16) unsigned short g_Blo[(size_t)NCOL * Hv];

// ---------------- helpers ----------------------------------------------------
__device__ __forceinline__ uint32_t smem_u32(const void* p) {
    uint32_t a;
    asm("{ .reg .u64 t; cvta.to.shared.u64 t, %1; cvt.u32.u64 %0, t; }"
        : "=r"(a) : "l"(p));
    return a;
}
__device__ __forceinline__ uint32_t sw128(uint32_t b) {
    return b ^ ((b >> 3) & 0x70);
}
#define CP16(dst, src) asm volatile( \
    "cp.async.cg.shared.global [%0], [%1], 16;" :: "r"(dst), "l"(src))
#define CP_COMMIT() asm volatile("cp.async.commit_group;" ::: "memory")
#define CP_WAIT1() asm volatile("cp.async.wait_group 1;" ::: "memory")
#define CP_WAIT0() asm volatile("cp.async.wait_group 0;" ::: "memory")

__device__ __forceinline__ void ldsm4(uint32_t addr, uint32_t* r) {
    asm volatile("ldmatrix.sync.aligned.m8n8.x4.shared.b16 {%0,%1,%2,%3}, [%4];"
                 : "=r"(r[0]), "=r"(r[1]), "=r"(r[2]), "=r"(r[3]) : "r"(addr));
}
__device__ __forceinline__ void mma16816(float* d, const uint32_t* a,
                                         const uint32_t* b) {
    asm volatile(
        "mma.sync.aligned.m16n8k16.row.col.f32.bf16.bf16.f32 "
        "{%0,%1,%2,%3}, {%4,%5,%6,%7}, {%8,%9}, {%0,%1,%2,%3};"
        : "+f"(d[0]), "+f"(d[1]), "+f"(d[2]), "+f"(d[3])
        : "r"(a[0]), "r"(a[1]), "r"(a[2]), "r"(a[3]), "r"(b[0]), "r"(b[1]));
}

__device__ __forceinline__ void split_bf16(float x, unsigned short& h,
                                           unsigned short& l) {
    __nv_bfloat16 hb = __float2bfloat16_rn(x);
    __nv_bfloat16 lb = __float2bfloat16_rn(x - __bfloat162float(hb));
    h = *(unsigned short*)&hb;
    l = *(unsigned short*)&lb;
}

// ---------------------------------------------------------------------------
// Convert 1: hidden_states -> hi/lo bf16 (row-major [4096, 2048])
// ---------------------------------------------------------------------------
__global__ void conv_a_kernel(const float* __restrict__ hs) {
    size_t i4 = (size_t)blockIdx.x * blockDim.x + threadIdx.x;
    float4 x = *(const float4*)&hs[i4 * 4];
    unsigned short h[4], l[4];
    split_bf16(x.x, h[0], l[0]);
    split_bf16(x.y, h[1], l[1]);
    split_bf16(x.z, h[2], l[2]);
    split_bf16(x.w, h[3], l[3]);
    *(uint2*)&g_Ahi[i4 * 4] = *(uint2*)h;
    *(uint2*)&g_Alo[i4 * 4] = *(uint2*)l;
}

// ---------------------------------------------------------------------------
// Convert 2: W (Q heads, K, V) -> K-major Bt [2304, 2048]: Bt[u*128+d][k]=W_u[k][d]
// ---------------------------------------------------------------------------
__global__ void conv_b_kernel(const float* __restrict__ Wq,
                              const float* __restrict__ Wk,
                              const float* __restrict__ Wv) {
    __shared__ float t[32][33];
    int n0 = blockIdx.x * 32;
    int k0 = blockIdx.y * 32;
    int u = n0 >> 7;
    int d0 = n0 & 127;
    const float* W = (u < Nv) ? (Wq + (size_t)u * Hv * Dv)
                              : ((u == Nv) ? Wk : Wv);
#pragma unroll
    for (int i = 0; i < 4; i++) {
        int k = k0 + threadIdx.y + i * 8;
        t[threadIdx.y + i * 8][threadIdx.x] = W[(size_t)k * Dv + d0 + threadIdx.x];
    }
    __syncthreads();
#pragma unroll
    for (int i = 0; i < 4; i++) {
        int r = threadIdx.y + i * 8;
        float v = t[threadIdx.x][r];
        unsigned short h, l;
        split_bf16(v, h, l);
        size_t o = (size_t)(n0 + r) * Hv + k0 + threadIdx.x;
        g_Bhi[o] = h;
        g_Blo[o] = l;
    }
}

// ---------------------------------------------------------------------------
// bf16x3 projection GEMM with mma.sync (HMMA).
// C[4096, 2304] = A @ Bt^T.  CTA tile 128x128, grid (32, 18), 256 threads.
// 8 warps = 4(M) x 2(N); warp tile 32x64.  K chunks of 64 bf16 (SW128 rows).
// smem: 2 stages x (Ahi|Alo|Bhi|Blo each 16KB) = 128 KB, cp.async dbl-buffer.
// ---------------------------------------------------------------------------
#define PSTAGE 65536
#define NCHUNK 32

__global__ __launch_bounds__(256, 1) void proj_mma_kernel(
    const float* __restrict__ bq, const float* __restrict__ bk,
    const float* __restrict__ bv)
{
    extern __shared__ __align__(1024) char smem[];
    const int tid = threadIdx.x;
    const int lane = tid & 31;
    const int w = tid >> 5;
    const int wm = w & 3;          // 0..3 -> M offset 32*wm
    const int wn = w >> 2;         // 0..1 -> N offset 64*wn
    const int m0 = blockIdx.x * 128;
    const int by = blockIdx.y;     // one output unit (head / K / V)
    const int n0 = by * 128;
    const uint32_t sbase = smem_u32(smem);

    float acc[2][8][4];
#pragma unroll
    for (int mt = 0; mt < 2; mt++)
#pragma unroll
        for (int nt = 0; nt < 8; nt++)
#pragma unroll
            for (int i = 0; i < 4; i++) acc[mt][nt][i] = 0.f;

    auto load_chunk = [&](uint32_t sb, int c) {
        const int k0 = c * 64;
#pragma unroll
        for (int i = 0; i < 4; i++) {
            int idx = tid + 256 * i;
            int r = idx >> 3, col = idx & 7;
            uint32_t off = sw128(r * 128 + col * 16);
            CP16(sb + off,         &g_Ahi[(size_t)(m0 + r) * Hv + k0 + col * 8]);
            CP16(sb + 16384 + off, &g_Alo[(size_t)(m0 + r) * Hv + k0 + col * 8]);
            CP16(sb + 32768 + off, &g_Bhi[(size_t)(n0 + r) * Hv + k0 + col * 8]);
            CP16(sb + 49152 + off, &g_Blo[(size_t)(n0 + r) * Hv + k0 + col * 8]);
        }
    };

    // ldmatrix lane-address components (constant over chunks)
    const int a_row = wm * 32 + (lane & 15);          // + mt*16
    const int a_k16 = lane >> 4;                      // 16B unit within kstep
    const int b_row0 = wn * 64 + (lane & 7) + ((lane >> 4) << 3);  // + p*16
    const int b_k16 = (lane >> 3) & 1;

    load_chunk(sbase, 0);
    CP_COMMIT();

    for (int c = 0; c < NCHUNK; c++) {
        const uint32_t sb = sbase + (uint32_t)(c & 1) * PSTAGE;
        if (c + 1 < NCHUNK) {
            load_chunk(sbase + (uint32_t)((c + 1) & 1) * PSTAGE, c + 1);
            CP_COMMIT();
            CP_WAIT1();
        } else {
            CP_WAIT0();
        }
        __syncthreads();

#pragma unroll
        for (int ks = 0; ks < 4; ks++) {
            uint32_t ah[2][4], al[2][4], bh[4][4], bl[4][4];
#pragma unroll
            for (int mt = 0; mt < 2; mt++) {
                uint32_t off = sw128((a_row + mt * 16) * 128 +
                                     (ks * 2 + a_k16) * 16);
                ldsm4(sb + off, ah[mt]);
                ldsm4(sb + 16384 + off, al[mt]);
            }
#pragma unroll
            for (int p = 0; p < 4; p++) {
                uint32_t off = sw128((b_row0 + p * 16) * 128 +
                                     (ks * 2 + b_k16) * 16);
                ldsm4(sb + 32768 + off, bh[p]);
                ldsm4(sb + 49152 + off, bl[p]);
            }
#pragma unroll
            for (int mt = 0; mt < 2; mt++)
#pragma unroll
                for (int nt = 0; nt < 8; nt++) {
                    const uint32_t* bhp = &bh[nt >> 1][(nt & 1) * 2];
                    const uint32_t* blp = &bl[nt >> 1][(nt & 1) * 2];
                    mma16816(acc[mt][nt], ah[mt], bhp);   // Ah*Bh
                    mma16816(acc[mt][nt], al[mt], bhp);   // Al*Bh
                    mma16816(acc[mt][nt], ah[mt], blp);   // Ah*Bl
                }
        }
        __syncthreads();
    }

    // ---- epilogue: bias add + scatter to g_Q / g_K / g_V --------------------
    const int u = by;
    const float* bias = (u < Nv) ? (bq + u * Dv) : ((u == Nv) ? bk : bv);
    const int qrow = lane >> 2;
    const int qcol = (lane & 3) * 2;

#pragma unroll
    for (int mt = 0; mt < 2; mt++) {
#pragma unroll
        for (int half = 0; half < 2; half++) {
            int mrow = m0 + wm * 32 + mt * 16 + qrow + half * 8;
            float* outp;
            if (u < Nv) {
                int b = mrow >> 10, s = mrow & 1023;
                outp = g_Q + ((size_t)(b * Nv + u) * Sv + s) * Dv;
            } else {
                outp = ((u == Nv) ? g_K : g_V) + (size_t)mrow * Dv;
            }
#pragma unroll
            for (int nt = 0; nt < 8; nt++) {
                int d = wn * 64 + nt * 8 + qcol;
                float2 st;
                st.x = acc[mt][nt][half * 2 + 0] + bias[d];
                st.y = acc[mt][nt][half * 2 + 1] + bias[d + 1];
                *(float2*)&outp[d] = st;
            }
        }
    }
}

// ---------------------------------------------------------------------------
// fp32 flash attention (unchanged — known good).
// ---------------------------------------------------------------------------
#define QSTR 132
#define SSTR 68

__global__ __launch_bounds__(256, 1) void attn_kernel(float* __restrict__ out)
{
    extern __shared__ float sm[];
    float* Qs  = sm;
    float* Ks  = Qs + 64 * QSTR;
    float* Vs  = Ks + 64 * QSTR;
    float* Ss  = Vs + 64 * QSTR;
    float* m_s = Ss + 64 * SSTR;
    float* l_s = m_s + 64;

    const int tid = threadIdx.x;
    const int tx = tid & 15;
    const int ty = tid >> 4;
    const int qt = blockIdx.x;
    const int n  = blockIdx.y;
    const int b  = blockIdx.z;

    const float* Qg = g_Q + ((size_t)(b * Nv + n) * Sv + qt * 64) * Dv;
    const float* Kg = g_K + (size_t)b * Sv * Dv;
    const float* Vg = g_V + (size_t)b * Sv * Dv;

#pragma unroll
    for (int i = 0; i < 8; i++) {
        int f = tid + 256 * i;
        int r = f >> 5;
        int c = (f & 31) * 4;
        *(float4*)&Qs[r * QSTR + c] = *(const float4*)&Qg[(size_t)r * Dv + c];
    }
    if (tid < 64) { m_s[tid] = -3.0e38f; l_s[tid] = 0.f; }

    float o[4][8];
#pragma unroll
    for (int i = 0; i < 4; i++)
#pragma unroll
        for (int j = 0; j < 8; j++) o[i][j] = 0.f;

    for (int t = 0; t < Sv / 64; t++) {
        __syncthreads();
        const float* Kt = Kg + (size_t)t * 64 * Dv;
        const float* Vt = Vg + (size_t)t * 64 * Dv;
#pragma unroll
        for (int i = 0; i < 8; i++) {
            int f = tid + 256 * i;
            int r = f >> 5;
            int c = (f & 31) * 4;
            *(float4*)&Ks[r * QSTR + c] = *(const float4*)&Kt[(size_t)r * Dv + c];
            *(float4*)&Vs[r * QSTR + c] = *(const float4*)&Vt[(size_t)r * Dv + c];
        }
        __syncthreads();

        float s[4][4];
#pragma unroll
        for (int i = 0; i < 4; i++)
#pragma unroll
            for (int j = 0; j < 4; j++) s[i][j] = 0.f;

#pragma unroll 8
        for (int d = 0; d < Dv; d += 4) {
            float4 qa[4], kb[4];
#pragma unroll
            for (int i = 0; i < 4; i++)
                qa[i] = *(float4*)&Qs[(ty * 4 + i) * QSTR + d];
#pragma unroll
            for (int j = 0; j < 4; j++)
                kb[j] = *(float4*)&Ks[(tx + j * 16) * QSTR + d];
#pragma unroll
            for (int i = 0; i < 4; i++)
#pragma unroll
                for (int j = 0; j < 4; j++) {
                    s[i][j] = fmaf(qa[i].x, kb[j].x, s[i][j]);
                    s[i][j] = fmaf(qa[i].y, kb[j].y, s[i][j]);
                    s[i][j] = fmaf(qa[i].z, kb[j].z, s[i][j]);
                    s[i][j] = fmaf(qa[i].w, kb[j].w, s[i][j]);
                }
        }

#pragma unroll
        for (int i = 0; i < 4; i++) {
            int row = ty * 4 + i;
            float tm = fmaxf(fmaxf(s[i][0], s[i][1]), fmaxf(s[i][2], s[i][3]));
#pragma unroll
            for (int off = 8; off >= 1; off >>= 1)
                tm = fmaxf(tm, __shfl_xor_sync(0xffffffffu, tm, off));
            float m_old = m_s[row];
            float m_new = fmaxf(m_old, tm);
            float ci = __expf(m_old - m_new);
            float p0 = __expf(s[i][0] - m_new);
            float p1 = __expf(s[i][1] - m_new);
            float p2 = __expf(s[i][2] - m_new);
            float p3 = __expf(s[i][3] - m_new);
            float rs = (p0 + p1) + (p2 + p3);
#pragma unroll
            for (int off = 8; off >= 1; off >>= 1)
                rs += __shfl_xor_sync(0xffffffffu, rs, off);
            if (tx == 0) {
                m_s[row] = m_new;
                l_s[row] = l_s[row] * ci + rs;
            }
            Ss[row * SSTR + 0 * 16 + tx] = p0;
            Ss[row * SSTR + 1 * 16 + tx] = p1;
            Ss[row * SSTR + 2 * 16 + tx] = p2;
            Ss[row * SSTR + 3 * 16 + tx] = p3;
#pragma unroll
            for (int jj = 0; jj < 8; jj++) o[i][jj] *= ci;
        }
        __syncthreads();

#pragma unroll 4
        for (int kk = 0; kk < 64; kk++) {
            float pv[4];
#pragma unroll
            for (int i = 0; i < 4; i++) pv[i] = Ss[(ty * 4 + i) * SSTR + kk];
            float4 v0 = *(float4*)&Vs[kk * QSTR + tx * 8];
            float4 v1 = *(float4*)&Vs[kk * QSTR + tx * 8 + 4];
#pragma unroll
            for (int i = 0; i < 4; i++) {
                o[i][0] = fmaf(pv[i], v0.x, o[i][0]);
                o[i][1] = fmaf(pv[i], v0.y, o[i][1]);
                o[i][2] = fmaf(pv[i], v0.z, o[i][2]);
                o[i][3] = fmaf(pv[i], v0.w, o[i][3]);
                o[i][4] = fmaf(pv[i], v1.x, o[i][4]);
                o[i][5] = fmaf(pv[i], v1.y, o[i][5]);
                o[i][6] = fmaf(pv[i], v1.z, o[i][6]);
                o[i][7] = fmaf(pv[i], v1.w, o[i][7]);
            }
        }
    }
    __syncthreads();

#pragma unroll
    for (int i = 0; i < 4; i++) {
        int row = ty * 4 + i;
        float inv = 1.0f / l_s[row];
        size_t base = ((size_t)(b * Nv + n) * Sv + qt * 64 + row) * Dv;
        float4 o0 = make_float4(o[i][0] * inv, o[i][1] * inv,
                                o[i][2] * inv, o[i][3] * inv);
        float4 o1 = make_float4(o[i][4] * inv, o[i][5] * inv,
                                o[i][6] * inv, o[i][7] * inv);
        *(float4*)&out[base + tx * 8] = o0;
        *(float4*)&out[base + tx * 8 + 4] = o1;
    }
}

// ---------------------------------------------------------------------------
extern "C" void kernel_launch(void* const* d_in, const int* in_sizes, int n_in,
                              void* d_out, int out_size)
{
    const float* hs = (const float*)d_in[0];
    const float* Wq = (const float*)d_in[1];
    const float* bq = (const float*)d_in[2];
    const float* Wk = (const float*)d_in[3];
    const float* bk = (const float*)d_in[4];
    const float* Wv = (const float*)d_in[5];
    const float* bv = (const float*)d_in[6];
    float* out = (float*)d_out;

    conv_a_kernel<<<(Bv * Sv * Hv / 4) / 256, 256>>>(hs);
    conv_b_kernel<<<dim3(NCOL / 32, Hv / 32), dim3(32, 8)>>>(Wq, Wk, Wv);

    const int proj_smem = 2 * PSTAGE;
    cudaFuncSetAttribute(proj_mma_kernel,
                         cudaFuncAttributeMaxDynamicSharedMemorySize, proj_smem);
    proj_mma_kernel<<<dim3(32, 18), 256, proj_smem>>>(bq, bk, bv);

    const int attn_smem = (64 * QSTR * 3 + 64 * SSTR + 128) * (int)sizeof(float);
    cudaFuncSetAttribute(attn_kernel,
                         cudaFuncAttributeMaxDynamicSharedMemorySize, attn_smem);
    dim3 ga(Sv / 64, Nv, Bv);
    attn_kernel<<<ga, 256, attn_smem>>>(out);
}

// round 4
// speedup vs baseline: 4.8556x; 2.8012x over previous
#include <cuda_runtime.h>
#include <cuda_bf16.h>
#include <cuda_fp16.h>
#include <cstdint>

#define Bv 4
#define Sv 1024
#define Hv 2048
#define Nv 16
#define Dv 128
#define NCOL 2304          // 18 * 128 fused output columns (16 Q heads, K, V)

// ---------------- device scratch (static: allocation-free) ------------------
__device__ __align__(16) unsigned short g_Ahi[(size_t)Bv * Sv * Hv];
__device__ __align__(16) unsigned short g_Alo[(size_t)Bv * Sv * Hv];
__device__ __align__(16) unsigned short g_Bhi[(size_t)NCOL * Hv];
__device__ __align__(16) unsigned short g_Blo[(size_t)NCOL * Hv];
__device__ __align__(16) unsigned short g_Qh[(size_t)Bv * Nv * Sv * Dv];
__device__ __align__(16) unsigned short g_Ql[(size_t)Bv * Nv * Sv * Dv];
__device__ __align__(16) unsigned short g_Kh[(size_t)Bv * Sv * Dv];
__device__ __align__(16) unsigned short g_Kl[(size_t)Bv * Sv * Dv];
__device__ __align__(16) __half         g_Vf[(size_t)Bv * Sv * Dv];

// ---------------- helpers ----------------------------------------------------
__device__ __forceinline__ uint32_t smem_u32(const void* p) {
    uint32_t a;
    asm("{ .reg .u64 t; cvta.to.shared.u64 t, %1; cvt.u32.u64 %0, t; }"
        : "=r"(a) : "l"(p));
    return a;
}
__device__ __forceinline__ uint32_t sw128(uint32_t b) {
    return b ^ ((b >> 3) & 0x70);
}
#define CP16(dst, src) asm volatile( \
    "cp.async.cg.shared.global [%0], [%1], 16;" :: "r"(dst), "l"(src))
#define CP_COMMIT() asm volatile("cp.async.commit_group;" ::: "memory")
#define CP_WAIT1() asm volatile("cp.async.wait_group 1;" ::: "memory")
#define CP_WAIT0() asm volatile("cp.async.wait_group 0;" ::: "memory")

__device__ __forceinline__ void ldsm4(uint32_t addr, uint32_t* r) {
    asm volatile("ldmatrix.sync.aligned.m8n8.x4.shared.b16 {%0,%1,%2,%3}, [%4];"
                 : "=r"(r[0]), "=r"(r[1]), "=r"(r[2]), "=r"(r[3]) : "r"(addr));
}
__device__ __forceinline__ void ldsm4t(uint32_t addr, uint32_t* r) {
    asm volatile("ldmatrix.sync.aligned.m8n8.x4.trans.shared.b16 {%0,%1,%2,%3}, [%4];"
                 : "=r"(r[0]), "=r"(r[1]), "=r"(r[2]), "=r"(r[3]) : "r"(addr));
}
__device__ __forceinline__ void mma16816(float* d, const uint32_t* a,
                                         const uint32_t* b) {
    asm volatile(
        "mma.sync.aligned.m16n8k16.row.col.f32.bf16.bf16.f32 "
        "{%0,%1,%2,%3}, {%4,%5,%6,%7}, {%8,%9}, {%0,%1,%2,%3};"
        : "+f"(d[0]), "+f"(d[1]), "+f"(d[2]), "+f"(d[3])
        : "r"(a[0]), "r"(a[1]), "r"(a[2]), "r"(a[3]), "r"(b[0]), "r"(b[1]));
}
__device__ __forceinline__ void mma16816h(float* d, const uint32_t* a,
                                          const uint32_t* b) {
    asm volatile(
        "mma.sync.aligned.m16n8k16.row.col.f32.f16.f16.f32 "
        "{%0,%1,%2,%3}, {%4,%5,%6,%7}, {%8,%9}, {%0,%1,%2,%3};"
        : "+f"(d[0]), "+f"(d[1]), "+f"(d[2]), "+f"(d[3])
        : "r"(a[0]), "r"(a[1]), "r"(a[2]), "r"(a[3]), "r"(b[0]), "r"(b[1]));
}

__device__ __forceinline__ void split_bf16(float x, unsigned short& h,
                                           unsigned short& l) {
    __nv_bfloat16 hb = __float2bfloat16_rn(x);
    __nv_bfloat16 lb = __float2bfloat16_rn(x - __bfloat162float(hb));
    h = *(unsigned short*)&hb;
    l = *(unsigned short*)&lb;
}
__device__ __forceinline__ uint32_t pack_h2(float a, float b) {
    __half2 h = __floats2half2_rn(a, b);
    return *(uint32_t*)&h;
}

// ---------------------------------------------------------------------------
// Convert 1: hidden_states -> hi/lo bf16 (row-major [4096, 2048])
// ---------------------------------------------------------------------------
__global__ void conv_a_kernel(const float* __restrict__ hs) {
    size_t i4 = (size_t)blockIdx.x * blockDim.x + threadIdx.x;
    float4 x = *(const float4*)&hs[i4 * 4];
    unsigned short h[4], l[4];
    split_bf16(x.x, h[0], l[0]);
    split_bf16(x.y, h[1], l[1]);
    split_bf16(x.z, h[2], l[2]);
    split_bf16(x.w, h[3], l[3]);
    *(uint2*)&g_Ahi[i4 * 4] = *(uint2*)h;
    *(uint2*)&g_Alo[i4 * 4] = *(uint2*)l;
}

// ---------------------------------------------------------------------------
// Convert 2: W -> K-major Bt [2304, 2048]: Bt[u*128+d][k] = W_u[k][d]
// ---------------------------------------------------------------------------
__global__ void conv_b_kernel(const float* __restrict__ Wq,
                              const float* __restrict__ Wk,
                              const float* __restrict__ Wv) {
    __shared__ float t[32][33];
    int n0 = blockIdx.x * 32;
    int k0 = blockIdx.y * 32;
    int u = n0 >> 7;
    int d0 = n0 & 127;
    const float* W = (u < Nv) ? (Wq + (size_t)u * Hv * Dv)
                              : ((u == Nv) ? Wk : Wv);
#pragma unroll
    for (int i = 0; i < 4; i++) {
        int k = k0 + threadIdx.y + i * 8;
        t[threadIdx.y + i * 8][threadIdx.x] = W[(size_t)k * Dv + d0 + threadIdx.x];
    }
    __syncthreads();
#pragma unroll
    for (int i = 0; i < 4; i++) {
        int r = threadIdx.y + i * 8;
        float v = t[threadIdx.x][r];
        unsigned short h, l;
        split_bf16(v, h, l);
        size_t o = (size_t)(n0 + r) * Hv + k0 + threadIdx.x;
        g_Bhi[o] = h;
        g_Blo[o] = l;
    }
}

// ---------------------------------------------------------------------------
// bf16x3 projection GEMM (HMMA). Epilogue now emits Q/K as split bf16 and
// V as fp16 directly (consumed by the tensor-core attention kernel).
// ---------------------------------------------------------------------------
#define PSTAGE 65536
#define NCHUNK 32

__global__ __launch_bounds__(256, 1) void proj_mma_kernel(
    const float* __restrict__ bq, const float* __restrict__ bk,
    const float* __restrict__ bv)
{
    extern __shared__ __align__(1024) char smem[];
    const int tid = threadIdx.x;
    const int lane = tid & 31;
    const int w = tid >> 5;
    const int wm = w & 3;
    const int wn = w >> 2;
    const int m0 = blockIdx.x * 128;
    const int by = blockIdx.y;
    const int n0 = by * 128;
    const uint32_t sbase = smem_u32(smem);

    float acc[2][8][4];
#pragma unroll
    for (int mt = 0; mt < 2; mt++)
#pragma unroll
        for (int nt = 0; nt < 8; nt++)
#pragma unroll
            for (int i = 0; i < 4; i++) acc[mt][nt][i] = 0.f;

    auto load_chunk = [&](uint32_t sb, int c) {
        const int k0 = c * 64;
#pragma unroll
        for (int i = 0; i < 4; i++) {
            int idx = tid + 256 * i;
            int r = idx >> 3, col = idx & 7;
            uint32_t off = sw128(r * 128 + col * 16);
            CP16(sb + off,         &g_Ahi[(size_t)(m0 + r) * Hv + k0 + col * 8]);
            CP16(sb + 16384 + off, &g_Alo[(size_t)(m0 + r) * Hv + k0 + col * 8]);
            CP16(sb + 32768 + off, &g_Bhi[(size_t)(n0 + r) * Hv + k0 + col * 8]);
            CP16(sb + 49152 + off, &g_Blo[(size_t)(n0 + r) * Hv + k0 + col * 8]);
        }
    };

    const int a_row = wm * 32 + (lane & 15);
    const int a_k16 = lane >> 4;
    const int b_row0 = wn * 64 + (lane & 7) + ((lane >> 4) << 3);
    const int b_k16 = (lane >> 3) & 1;

    load_chunk(sbase, 0);
    CP_COMMIT();

    for (int c = 0; c < NCHUNK; c++) {
        const uint32_t sb = sbase + (uint32_t)(c & 1) * PSTAGE;
        if (c + 1 < NCHUNK) {
            load_chunk(sbase + (uint32_t)((c + 1) & 1) * PSTAGE, c + 1);
            CP_COMMIT();
            CP_WAIT1();
        } else {
            CP_WAIT0();
        }
        __syncthreads();

#pragma unroll
        for (int ks = 0; ks < 4; ks++) {
            uint32_t ah[2][4], al[2][4], bh[4][4], bl[4][4];
#pragma unroll
            for (int mt = 0; mt < 2; mt++) {
                uint32_t off = sw128((a_row + mt * 16) * 128 +
                                     (ks * 2 + a_k16) * 16);
                ldsm4(sb + off, ah[mt]);
                ldsm4(sb + 16384 + off, al[mt]);
            }
#pragma unroll
            for (int p = 0; p < 4; p++) {
                uint32_t off = sw128((b_row0 + p * 16) * 128 +
                                     (ks * 2 + b_k16) * 16);
                ldsm4(sb + 32768 + off, bh[p]);
                ldsm4(sb + 49152 + off, bl[p]);
            }
#pragma unroll
            for (int mt = 0; mt < 2; mt++)
#pragma unroll
                for (int nt = 0; nt < 8; nt++) {
                    const uint32_t* bhp = &bh[nt >> 1][(nt & 1) * 2];
                    const uint32_t* blp = &bl[nt >> 1][(nt & 1) * 2];
                    mma16816(acc[mt][nt], ah[mt], bhp);
                    mma16816(acc[mt][nt], al[mt], bhp);
                    mma16816(acc[mt][nt], ah[mt], blp);
                }
        }
        __syncthreads();
    }

    // ---- epilogue: bias add + write split-bf16 (Q,K) / fp16 (V) -------------
    const int u = by;
    const float* bias = (u < Nv) ? (bq + u * Dv) : ((u == Nv) ? bk : bv);
    const int qrow = lane >> 2;
    const int qcol = (lane & 3) * 2;

#pragma unroll
    for (int mt = 0; mt < 2; mt++) {
#pragma unroll
        for (int half = 0; half < 2; half++) {
            int mrow = m0 + wm * 32 + mt * 16 + qrow + half * 8;
            size_t base;
            if (u < Nv) {
                int b = mrow >> 10, s = mrow & 1023;
                base = ((size_t)(b * Nv + u) * Sv + s) * Dv;
            } else {
                base = (size_t)mrow * Dv;
            }
#pragma unroll
            for (int nt = 0; nt < 8; nt++) {
                int d = wn * 64 + nt * 8 + qcol;
                float x = acc[mt][nt][half * 2 + 0] + bias[d];
                float y = acc[mt][nt][half * 2 + 1] + bias[d + 1];
                if (u < Nv) {
                    unsigned short hx, lx, hy, ly;
                    split_bf16(x, hx, lx);
                    split_bf16(y, hy, ly);
                    ushort2 sh = make_ushort2(hx, hy);
                    ushort2 sl = make_ushort2(lx, ly);
                    *(ushort2*)&g_Qh[base + d] = sh;
                    *(ushort2*)&g_Ql[base + d] = sl;
                } else if (u == Nv) {
                    unsigned short hx, lx, hy, ly;
                    split_bf16(x, hx, lx);
                    split_bf16(y, hy, ly);
                    *(ushort2*)&g_Kh[base + d] = make_ushort2(hx, hy);
                    *(ushort2*)&g_Kl[base + d] = make_ushort2(lx, ly);
                } else {
                    __half2 v2 = __floats2half2_rn(x, y);
                    *(__half2*)&g_Vf[base + d] = v2;
                }
            }
        }
    }
}

// ---------------------------------------------------------------------------
// Tensor-core flash attention.
// grid (S/128, N, B), 256 threads (8 warps x 16 query rows).
// QK^T: bf16x3 (QhKh + QlKh + QhKl), fp32 accum.  PV: fp16 single, fp32 accum.
// KV streamed in 64-key tiles (Kh 16K | Kl 16K | Vf 16K), double-buffered.
// smem: Q 64KB + 2*48KB = 160KB.
// ---------------------------------------------------------------------------
#define KV_STAGE 49152

__global__ __launch_bounds__(256, 1) void attn_mma_kernel(float* __restrict__ out)
{
    extern __shared__ __align__(1024) char smem[];
    const int tid = threadIdx.x;
    const int lane = tid & 31;
    const int w = tid >> 5;
    const int qt = blockIdx.x;
    const int n = blockIdx.y;
    const int b = blockIdx.z;

    const uint32_t sQh = smem_u32(smem);
    const uint32_t sQl = sQh + 32768;
    const uint32_t sKV = sQh + 65536;

    const size_t qoff = ((size_t)(b * Nv + n) * Sv + qt * 128) * Dv;
    const unsigned short* Qh = g_Qh + qoff;
    const unsigned short* Ql = g_Ql + qoff;
    const unsigned short* Kh = g_Kh + (size_t)b * Sv * Dv;
    const unsigned short* Kl = g_Kl + (size_t)b * Sv * Dv;
    const __half* Vf = g_Vf + (size_t)b * Sv * Dv;

    // Q tile: per array 2048 16B units, 8 per thread. Chunk stride 16KB.
#pragma unroll
    for (int i = 0; i < 8; i++) {
        int idx = tid + 256 * i;
        int r = idx >> 4, c16 = idx & 15;
        uint32_t off = (uint32_t)(c16 >> 3) * 16384 +
                       sw128(r * 128 + (c16 & 7) * 16);
        CP16(sQh + off, Qh + (size_t)r * Dv + c16 * 8);
        CP16(sQl + off, Ql + (size_t)r * Dv + c16 * 8);
    }

    auto load_kv = [&](int t) {
        uint32_t dst = sKV + (uint32_t)(t & 1) * KV_STAGE;
        int r0 = t * 64;
#pragma unroll
        for (int i = 0; i < 4; i++) {
            int idx = tid + 256 * i;
            int r = idx >> 4, c16 = idx & 15;
            uint32_t off = (uint32_t)(c16 >> 3) * 8192 +
                           sw128(r * 128 + (c16 & 7) * 16);
            CP16(dst + off,         Kh + (size_t)(r0 + r) * Dv + c16 * 8);
            CP16(dst + 16384 + off, Kl + (size_t)(r0 + r) * Dv + c16 * 8);
            CP16(dst + 32768 + off, Vf + (size_t)(r0 + r) * Dv + c16 * 8);
        }
    };

    load_kv(0);
    CP_COMMIT();

    float o[16][4];
#pragma unroll
    for (int nt = 0; nt < 16; nt++)
#pragma unroll
        for (int i = 0; i < 4; i++) o[nt][i] = 0.f;
    float mrun[2] = {-3.0e38f, -3.0e38f};
    float lrun[2] = {0.f, 0.f};

    for (int t = 0; t < Sv / 64; t++) {
        const uint32_t kb = sKV + (uint32_t)(t & 1) * KV_STAGE;
        if (t + 1 < Sv / 64) {
            load_kv(t + 1);
            CP_COMMIT();
            CP_WAIT1();
        } else {
            CP_WAIT0();
        }
        __syncthreads();

        // ---- S = Q K^T over 64 keys (8 k16 steps over D=128) ---------------
        float s[8][4];
#pragma unroll
        for (int nt = 0; nt < 8; nt++)
#pragma unroll
            for (int i = 0; i < 4; i++) s[nt][i] = 0.f;

#pragma unroll
        for (int kk = 0; kk < 8; kk++) {
            uint32_t qo = (uint32_t)(kk >> 2) * 16384 +
                sw128((w * 16 + (lane & 15)) * 128 +
                      ((kk & 3) * 2 + (lane >> 4)) * 16);
            uint32_t ah[4], al[4];
            ldsm4(sQh + qo, ah);
            ldsm4(sQl + qo, al);
            uint32_t kcol = ((kk & 3) * 2 + ((lane >> 3) & 1)) * 16;
#pragma unroll
            for (int p = 0; p < 4; p++) {
                uint32_t ko = (uint32_t)(kk >> 2) * 8192 +
                    sw128((p * 16 + (lane & 7) + ((lane >> 4) << 3)) * 128 + kcol);
                uint32_t bh[4], bl[4];
                ldsm4(kb + ko, bh);
                ldsm4(kb + 16384 + ko, bl);
#pragma unroll
                for (int q = 0; q < 2; q++) {
                    int nt = p * 2 + q;
                    mma16816(s[nt], ah, &bh[q * 2]);
                    mma16816(s[nt], al, &bh[q * 2]);
                    mma16816(s[nt], ah, &bl[q * 2]);
                }
            }
        }

        // ---- online softmax (rows owned per quad; shfl xor 1,2) -------------
        float tmax[2] = {-3.0e38f, -3.0e38f};
#pragma unroll
        for (int nt = 0; nt < 8; nt++) {
            tmax[0] = fmaxf(tmax[0], fmaxf(s[nt][0], s[nt][1]));
            tmax[1] = fmaxf(tmax[1], fmaxf(s[nt][2], s[nt][3]));
        }
#pragma unroll
        for (int off = 1; off <= 2; off <<= 1) {
            tmax[0] = fmaxf(tmax[0], __shfl_xor_sync(0xffffffffu, tmax[0], off));
            tmax[1] = fmaxf(tmax[1], __shfl_xor_sync(0xffffffffu, tmax[1], off));
        }
        float mnew[2], ci[2];
#pragma unroll
        for (int h = 0; h < 2; h++) {
            mnew[h] = fmaxf(mrun[h], tmax[h]);
            ci[h] = __expf(mrun[h] - mnew[h]);
            mrun[h] = mnew[h];
        }

        uint32_t plo[8], phi[8];
        float rs[2] = {0.f, 0.f};
#pragma unroll
        for (int nt = 0; nt < 8; nt++) {
            float p0 = __expf(s[nt][0] - mnew[0]);
            float p1 = __expf(s[nt][1] - mnew[0]);
            float p2 = __expf(s[nt][2] - mnew[1]);
            float p3 = __expf(s[nt][3] - mnew[1]);
            rs[0] += p0 + p1;
            rs[1] += p2 + p3;
            plo[nt] = pack_h2(p0, p1);
            phi[nt] = pack_h2(p2, p3);
        }
#pragma unroll
        for (int off = 1; off <= 2; off <<= 1) {
            rs[0] += __shfl_xor_sync(0xffffffffu, rs[0], off);
            rs[1] += __shfl_xor_sync(0xffffffffu, rs[1], off);
        }
        lrun[0] = lrun[0] * ci[0] + rs[0];
        lrun[1] = lrun[1] * ci[1] + rs[1];
#pragma unroll
        for (int nt = 0; nt < 16; nt++) {
            o[nt][0] *= ci[0];
            o[nt][1] *= ci[0];
            o[nt][2] *= ci[1];
            o[nt][3] *= ci[1];
        }

        // ---- O += P @ V (fp16), V as B via ldmatrix.trans --------------------
#pragma unroll
        for (int kk2 = 0; kk2 < 4; kk2++) {
            uint32_t a[4] = {plo[2 * kk2], phi[2 * kk2],
                             plo[2 * kk2 + 1], phi[2 * kk2 + 1]};
            uint32_t kvr = kk2 * 16 + (lane & 7) + (((lane >> 3) & 1) << 3);
#pragma unroll
            for (int dt = 0; dt < 8; dt++) {
                uint32_t dcol = dt * 16 + ((lane >> 4) << 3);
                uint32_t off = (uint32_t)(dcol >> 6) * 8192 +
                               sw128(kvr * 128 + (dcol & 63) * 2);
                uint32_t bv4[4];
                ldsm4t(kb + 32768 + off, bv4);
                mma16816h(o[dt * 2],     a, &bv4[0]);
                mma16816h(o[dt * 2 + 1], a, &bv4[2]);
            }
        }
        __syncthreads();
    }

    // ---- normalize + store ---------------------------------------------------
    const float inv0 = 1.0f / lrun[0];
    const float inv1 = 1.0f / lrun[1];
    const int row0 = qt * 128 + w * 16 + (lane >> 2);
    const size_t ob = ((size_t)(b * Nv + n) * Sv) * Dv;
#pragma unroll
    for (int nt = 0; nt < 16; nt++) {
        int d = nt * 8 + (lane & 3) * 2;
        *(float2*)&out[ob + (size_t)row0 * Dv + d] =
            make_float2(o[nt][0] * inv0, o[nt][1] * inv0);
        *(float2*)&out[ob + (size_t)(row0 + 8) * Dv + d] =
            make_float2(o[nt][2] * inv1, o[nt][3] * inv1);
    }
}

// ---------------------------------------------------------------------------
extern "C" void kernel_launch(void* const* d_in, const int* in_sizes, int n_in,
                              void* d_out, int out_size)
{
    const float* hs = (const float*)d_in[0];
    const float* Wq = (const float*)d_in[1];
    const float* bq = (const float*)d_in[2];
    const float* Wk = (const float*)d_in[3];
    const float* bk = (const float*)d_in[4];
    const float* Wv = (const float*)d_in[5];
    const float* bv = (const float*)d_in[6];
    float* out = (float*)d_out;

    conv_a_kernel<<<(Bv * Sv * Hv / 4) / 256, 256>>>(hs);
    conv_b_kernel<<<dim3(NCOL / 32, Hv / 32), dim3(32, 8)>>>(Wq, Wk, Wv);

    const int proj_smem = 2 * PSTAGE;
    cudaFuncSetAttribute(proj_mma_kernel,
                         cudaFuncAttributeMaxDynamicSharedMemorySize, proj_smem);
    proj_mma_kernel<<<dim3(32, 18), 256, proj_smem>>>(bq, bk, bv);

    const int attn_smem = 65536 + 2 * KV_STAGE;   // 160 KB
    cudaFuncSetAttribute(attn_mma_kernel,
                         cudaFuncAttributeMaxDynamicSharedMemorySize, attn_smem);
    dim3 ga(Sv / 128, Nv, Bv);
    attn_mma_kernel<<<ga, 256, attn_smem>>>(out);
}

// round 5
// speedup vs baseline: 4.9280x; 1.0149x over previous
#include <cuda_runtime.h>
#include <cuda_bf16.h>
#include <cuda_fp16.h>
#include <cstdint>

#define Bv 4
#define Sv 1024
#define Hv 2048
#define Nv 16
#define Dv 128
#define NCOL 2304          // 18 * 128 fused output columns (16 Q heads, K, V)

// ---------------- device scratch (static: allocation-free) ------------------
__device__ __align__(16) unsigned short g_Ahi[(size_t)Bv * Sv * Hv];
__device__ __align__(16) unsigned short g_Alo[(size_t)Bv * Sv * Hv];
__device__ __align__(16) unsigned short g_Bhi[(size_t)NCOL * Hv];
__device__ __align__(16) unsigned short g_Blo[(size_t)NCOL * Hv];
__device__ __align__(16) unsigned short g_Qh[(size_t)Bv * Nv * Sv * Dv];
__device__ __align__(16) unsigned short g_Ql[(size_t)Bv * Nv * Sv * Dv];
__device__ __align__(16) unsigned short g_Kh[(size_t)Bv * Sv * Dv];
__device__ __align__(16) unsigned short g_Kl[(size_t)Bv * Sv * Dv];
__device__ __align__(16) __half         g_Vf[(size_t)Bv * Sv * Dv];

// ---------------- helpers ----------------------------------------------------
__device__ __forceinline__ uint32_t smem_u32(const void* p) {
    uint32_t a;
    asm("{ .reg .u64 t; cvta.to.shared.u64 t, %1; cvt.u32.u64 %0, t; }"
        : "=r"(a) : "l"(p));
    return a;
}
__device__ __forceinline__ uint32_t sw128(uint32_t b) {
    return b ^ ((b >> 3) & 0x70);
}
#define CP16(dst, src) asm volatile( \
    "cp.async.cg.shared.global [%0], [%1], 16;" :: "r"(dst), "l"(src))
#define CP_COMMIT() asm volatile("cp.async.commit_group;" ::: "memory")
#define CP_WAIT2() asm volatile("cp.async.wait_group 2;" ::: "memory")
#define CP_WAIT0() asm volatile("cp.async.wait_group 0;" ::: "memory")

__device__ __forceinline__ void ldsm4(uint32_t addr, uint32_t* r) {
    asm volatile("ldmatrix.sync.aligned.m8n8.x4.shared.b16 {%0,%1,%2,%3}, [%4];"
                 : "=r"(r[0]), "=r"(r[1]), "=r"(r[2]), "=r"(r[3]) : "r"(addr));
}
__device__ __forceinline__ void ldsm4t(uint32_t addr, uint32_t* r) {
    asm volatile("ldmatrix.sync.aligned.m8n8.x4.trans.shared.b16 {%0,%1,%2,%3}, [%4];"
                 : "=r"(r[0]), "=r"(r[1]), "=r"(r[2]), "=r"(r[3]) : "r"(addr));
}
__device__ __forceinline__ void mma16816(float* d, const uint32_t* a,
                                         const uint32_t* b) {
    asm volatile(
        "mma.sync.aligned.m16n8k16.row.col.f32.bf16.bf16.f32 "
        "{%0,%1,%2,%3}, {%4,%5,%6,%7}, {%8,%9}, {%0,%1,%2,%3};"
        : "+f"(d[0]), "+f"(d[1]), "+f"(d[2]), "+f"(d[3])
        : "r"(a[0]), "r"(a[1]), "r"(a[2]), "r"(a[3]), "r"(b[0]), "r"(b[1]));
}
__device__ __forceinline__ void mma16816h(float* d, const uint32_t* a,
                                          const uint32_t* b) {
    asm volatile(
        "mma.sync.aligned.m16n8k16.row.col.f32.f16.f16.f32 "
        "{%0,%1,%2,%3}, {%4,%5,%6,%7}, {%8,%9}, {%0,%1,%2,%3};"
        : "+f"(d[0]), "+f"(d[1]), "+f"(d[2]), "+f"(d[3])
        : "r"(a[0]), "r"(a[1]), "r"(a[2]), "r"(a[3]), "r"(b[0]), "r"(b[1]));
}

__device__ __forceinline__ void split_bf16(float x, unsigned short& h,
                                           unsigned short& l) {
    __nv_bfloat16 hb = __float2bfloat16_rn(x);
    __nv_bfloat16 lb = __float2bfloat16_rn(x - __bfloat162float(hb));
    h = *(unsigned short*)&hb;
    l = *(unsigned short*)&lb;
}
__device__ __forceinline__ uint32_t pack_h2(float a, float b) {
    __half2 h = __floats2half2_rn(a, b);
    return *(uint32_t*)&h;
}

// ---------------------------------------------------------------------------
// Convert 1: hidden_states -> hi/lo bf16 (row-major [4096, 2048])
// ---------------------------------------------------------------------------
__global__ void conv_a_kernel(const float* __restrict__ hs) {
    size_t i4 = (size_t)blockIdx.x * blockDim.x + threadIdx.x;
    float4 x = *(const float4*)&hs[i4 * 4];
    unsigned short h[4], l[4];
    split_bf16(x.x, h[0], l[0]);
    split_bf16(x.y, h[1], l[1]);
    split_bf16(x.z, h[2], l[2]);
    split_bf16(x.w, h[3], l[3]);
    *(uint2*)&g_Ahi[i4 * 4] = *(uint2*)h;
    *(uint2*)&g_Alo[i4 * 4] = *(uint2*)l;
}

// ---------------------------------------------------------------------------
// Convert 2: W -> K-major Bt [2304, 2048]: Bt[u*128+d][k] = W_u[k][d]
// ---------------------------------------------------------------------------
__global__ void conv_b_kernel(const float* __restrict__ Wq,
                              const float* __restrict__ Wk,
                              const float* __restrict__ Wv) {
    __shared__ float t[32][33];
    int n0 = blockIdx.x * 32;
    int k0 = blockIdx.y * 32;
    int u = n0 >> 7;
    int d0 = n0 & 127;
    const float* W = (u < Nv) ? (Wq + (size_t)u * Hv * Dv)
                              : ((u == Nv) ? Wk : Wv);
#pragma unroll
    for (int i = 0; i < 4; i++) {
        int k = k0 + threadIdx.y + i * 8;
        t[threadIdx.y + i * 8][threadIdx.x] = W[(size_t)k * Dv + d0 + threadIdx.x];
    }
    __syncthreads();
#pragma unroll
    for (int i = 0; i < 4; i++) {
        int r = threadIdx.y + i * 8;
        float v = t[threadIdx.x][r];
        unsigned short h, l;
        split_bf16(v, h, l);
        size_t o = (size_t)(n0 + r) * Hv + k0 + threadIdx.x;
        g_Bhi[o] = h;
        g_Blo[o] = l;
    }
}

// ---------------------------------------------------------------------------
// bf16x3 projection GEMM (HMMA). Single sync per k-chunk iteration.
// ---------------------------------------------------------------------------
#define PSTAGE 65536
#define NCHUNK 32

__global__ __launch_bounds__(256, 1) void proj_mma_kernel(
    const float* __restrict__ bq, const float* __restrict__ bk,
    const float* __restrict__ bv)
{
    extern __shared__ __align__(1024) char smem[];
    const int tid = threadIdx.x;
    const int lane = tid & 31;
    const int w = tid >> 5;
    const int wm = w & 3;
    const int wn = w >> 2;
    const int m0 = blockIdx.x * 128;
    const int by = blockIdx.y;
    const int n0 = by * 128;
    const uint32_t sbase = smem_u32(smem);

    float acc[2][8][4];
#pragma unroll
    for (int mt = 0; mt < 2; mt++)
#pragma unroll
        for (int nt = 0; nt < 8; nt++)
#pragma unroll
            for (int i = 0; i < 4; i++) acc[mt][nt][i] = 0.f;

    auto load_chunk = [&](uint32_t sb, int c) {
        const int k0 = c * 64;
#pragma unroll
        for (int i = 0; i < 4; i++) {
            int idx = tid + 256 * i;
            int r = idx >> 3, col = idx & 7;
            uint32_t off = sw128(r * 128 + col * 16);
            CP16(sb + off,         &g_Ahi[(size_t)(m0 + r) * Hv + k0 + col * 8]);
            CP16(sb + 16384 + off, &g_Alo[(size_t)(m0 + r) * Hv + k0 + col * 8]);
            CP16(sb + 32768 + off, &g_Bhi[(size_t)(n0 + r) * Hv + k0 + col * 8]);
            CP16(sb + 49152 + off, &g_Blo[(size_t)(n0 + r) * Hv + k0 + col * 8]);
        }
    };

    const int a_row = wm * 32 + (lane & 15);
    const int a_k16 = lane >> 4;
    const int b_row0 = wn * 64 + (lane & 7) + ((lane >> 4) << 3);
    const int b_k16 = (lane >> 3) & 1;

    load_chunk(sbase, 0);
    CP_COMMIT();

    for (int c = 0; c < NCHUNK; c++) {
        const uint32_t sb = sbase + (uint32_t)(c & 1) * PSTAGE;
        CP_WAIT0();
        __syncthreads();                      // all warps done with prev chunk
        if (c + 1 < NCHUNK) {
            load_chunk(sbase + (uint32_t)((c + 1) & 1) * PSTAGE, c + 1);
            CP_COMMIT();
        }

#pragma unroll
        for (int ks = 0; ks < 4; ks++) {
            uint32_t ah[2][4], al[2][4], bh[4][4], bl[4][4];
#pragma unroll
            for (int mt = 0; mt < 2; mt++) {
                uint32_t off = sw128((a_row + mt * 16) * 128 +
                                     (ks * 2 + a_k16) * 16);
                ldsm4(sb + off, ah[mt]);
                ldsm4(sb + 16384 + off, al[mt]);
            }
#pragma unroll
            for (int p = 0; p < 4; p++) {
                uint32_t off = sw128((b_row0 + p * 16) * 128 +
                                     (ks * 2 + b_k16) * 16);
                ldsm4(sb + 32768 + off, bh[p]);
                ldsm4(sb + 49152 + off, bl[p]);
            }
#pragma unroll
            for (int mt = 0; mt < 2; mt++)
#pragma unroll
                for (int nt = 0; nt < 8; nt++) {
                    const uint32_t* bhp = &bh[nt >> 1][(nt & 1) * 2];
                    const uint32_t* blp = &bl[nt >> 1][(nt & 1) * 2];
                    mma16816(acc[mt][nt], ah[mt], bhp);
                    mma16816(acc[mt][nt], al[mt], bhp);
                    mma16816(acc[mt][nt], ah[mt], blp);
                }
        }
    }

    // ---- epilogue: bias add + write split-bf16 (Q,K) / fp16 (V) -------------
    const int u = by;
    const float* bias = (u < Nv) ? (bq + u * Dv) : ((u == Nv) ? bk : bv);
    const int qrow = lane >> 2;
    const int qcol = (lane & 3) * 2;

#pragma unroll
    for (int mt = 0; mt < 2; mt++) {
#pragma unroll
        for (int half = 0; half < 2; half++) {
            int mrow = m0 + wm * 32 + mt * 16 + qrow + half * 8;
            size_t base;
            if (u < Nv) {
                int b = mrow >> 10, s = mrow & 1023;
                base = ((size_t)(b * Nv + u) * Sv + s) * Dv;
            } else {
                base = (size_t)mrow * Dv;
            }
#pragma unroll
            for (int nt = 0; nt < 8; nt++) {
                int d = wn * 64 + nt * 8 + qcol;
                float x = acc[mt][nt][half * 2 + 0] + bias[d];
                float y = acc[mt][nt][half * 2 + 1] + bias[d + 1];
                if (u < Nv) {
                    unsigned short hx, lx, hy, ly;
                    split_bf16(x, hx, lx);
                    split_bf16(y, hy, ly);
                    *(ushort2*)&g_Qh[base + d] = make_ushort2(hx, hy);
                    *(ushort2*)&g_Ql[base + d] = make_ushort2(lx, ly);
                } else if (u == Nv) {
                    unsigned short hx, lx, hy, ly;
                    split_bf16(x, hx, lx);
                    split_bf16(y, hy, ly);
                    *(ushort2*)&g_Kh[base + d] = make_ushort2(hx, hy);
                    *(ushort2*)&g_Kl[base + d] = make_ushort2(lx, ly);
                } else {
                    __half2 v2 = __floats2half2_rn(x, y);
                    *(__half2*)&g_Vf[base + d] = v2;
                }
            }
        }
    }
}

// ---------------------------------------------------------------------------
// Tensor-core flash attention, v2.
// grid (S/128, N, B), 256 threads (8 warps x 16 query rows).
// Q fragments hoisted to registers (loaded once); smem = 4-stage KV pipeline.
// One __syncthreads per KV tile; per-lane softmax denominator partials.
// ---------------------------------------------------------------------------
#define KV_STAGE 49152
#define NKV (Sv / 64)

__global__ __launch_bounds__(256, 1) void attn_mma_kernel(float* __restrict__ out)
{
    extern __shared__ __align__(1024) char smem[];
    const int tid = threadIdx.x;
    const int lane = tid & 31;
    const int w = tid >> 5;
    const int qt = blockIdx.x;
    const int n = blockIdx.y;
    const int b = blockIdx.z;

    const uint32_t sb0 = smem_u32(smem);

    // ---- Q prologue: stage Q through smem, hoist fragments to registers ----
    const size_t qoff = ((size_t)(b * Nv + n) * Sv + qt * 128) * Dv;
    const unsigned short* Qh = g_Qh + qoff;
    const unsigned short* Ql = g_Ql + qoff;
#pragma unroll
    for (int i = 0; i < 8; i++) {
        int idx = tid + 256 * i;
        int r = idx >> 4, c16 = idx & 15;
        uint32_t off = (uint32_t)(c16 >> 3) * 16384 +
                       sw128(r * 128 + (c16 & 7) * 16);
        CP16(sb0 + off,         Qh + (size_t)r * Dv + c16 * 8);
        CP16(sb0 + 32768 + off, Ql + (size_t)r * Dv + c16 * 8);
    }
    CP_COMMIT();
    CP_WAIT0();
    __syncthreads();

    uint32_t ah[8][4], al[8][4];
#pragma unroll
    for (int kk = 0; kk < 8; kk++) {
        uint32_t qo = (uint32_t)(kk >> 2) * 16384 +
            sw128((w * 16 + (lane & 15)) * 128 +
                  ((kk & 3) * 2 + (lane >> 4)) * 16);
        ldsm4(sb0 + qo, ah[kk]);
        ldsm4(sb0 + 32768 + qo, al[kk]);
    }
    __syncthreads();     // Q smem region is now free for KV stages

    const unsigned short* Kh = g_Kh + (size_t)b * Sv * Dv;
    const unsigned short* Kl = g_Kl + (size_t)b * Sv * Dv;
    const __half* Vf = g_Vf + (size_t)b * Sv * Dv;

    auto load_kv = [&](int t) {
        uint32_t dst = sb0 + (uint32_t)(t & 3) * KV_STAGE;
        int r0 = t * 64;
#pragma unroll
        for (int i = 0; i < 4; i++) {
            int idx = tid + 256 * i;
            int r = idx >> 4, c16 = idx & 15;
            uint32_t off = (uint32_t)(c16 >> 3) * 8192 +
                           sw128(r * 128 + (c16 & 7) * 16);
            CP16(dst + off,         Kh + (size_t)(r0 + r) * Dv + c16 * 8);
            CP16(dst + 16384 + off, Kl + (size_t)(r0 + r) * Dv + c16 * 8);
            CP16(dst + 32768 + off, Vf + (size_t)(r0 + r) * Dv + c16 * 8);
        }
    };

    load_kv(0); CP_COMMIT();
    load_kv(1); CP_COMMIT();
    load_kv(2); CP_COMMIT();

    float o[16][4];
#pragma unroll
    for (int nt = 0; nt < 16; nt++)
#pragma unroll
        for (int i = 0; i < 4; i++) o[nt][i] = 0.f;
    float mrun[2] = {-3.0e38f, -3.0e38f};
    float lrun[2] = {0.f, 0.f};     // per-lane partials over owned columns

    for (int t = 0; t < NKV; t++) {
        CP_WAIT2();                  // group for tile t complete
        __syncthreads();             // all warps done reading buf (t-1)&3
        if (t + 3 < NKV) load_kv(t + 3);
        CP_COMMIT();                 // exactly one group per iteration
        const uint32_t kb = sb0 + (uint32_t)(t & 3) * KV_STAGE;

        // ---- S = Q K^T over 64 keys (Q fragments already in registers) ------
        float s[8][4];
#pragma unroll
        for (int nt = 0; nt < 8; nt++)
#pragma unroll
            for (int i = 0; i < 4; i++) s[nt][i] = 0.f;

#pragma unroll
        for (int kk = 0; kk < 8; kk++) {
            uint32_t kcol = ((kk & 3) * 2 + ((lane >> 3) & 1)) * 16;
#pragma unroll
            for (int p = 0; p < 4; p++) {
                uint32_t ko = (uint32_t)(kk >> 2) * 8192 +
                    sw128((p * 16 + (lane & 7) + ((lane >> 4) << 3)) * 128 + kcol);
                uint32_t bh[4], bl[4];
                ldsm4(kb + ko, bh);
                ldsm4(kb + 16384 + ko, bl);
#pragma unroll
                for (int q = 0; q < 2; q++) {
                    int nt = p * 2 + q;
                    mma16816(s[nt], ah[kk], &bh[q * 2]);
                    mma16816(s[nt], al[kk], &bh[q * 2]);
                    mma16816(s[nt], ah[kk], &bl[q * 2]);
                }
            }
        }

        // ---- online softmax: max via quad shfl, l kept as per-lane partial --
        float tmax[2] = {-3.0e38f, -3.0e38f};
#pragma unroll
        for (int nt = 0; nt < 8; nt++) {
            tmax[0] = fmaxf(tmax[0], fmaxf(s[nt][0], s[nt][1]));
            tmax[1] = fmaxf(tmax[1], fmaxf(s[nt][2], s[nt][3]));
        }
#pragma unroll
        for (int off = 1; off <= 2; off <<= 1) {
            tmax[0] = fmaxf(tmax[0], __shfl_xor_sync(0xffffffffu, tmax[0], off));
            tmax[1] = fmaxf(tmax[1], __shfl_xor_sync(0xffffffffu, tmax[1], off));
        }
        float mnew[2], ci[2];
#pragma unroll
        for (int h = 0; h < 2; h++) {
            mnew[h] = fmaxf(mrun[h], tmax[h]);
            ci[h] = __expf(mrun[h] - mnew[h]);
            mrun[h] = mnew[h];
        }

        uint32_t plo[8], phi[8];
        float rs0 = 0.f, rs1 = 0.f;
#pragma unroll
        for (int nt = 0; nt < 8; nt++) {
            float p0 = __expf(s[nt][0] - mnew[0]);
            float p1 = __expf(s[nt][1] - mnew[0]);
            float p2 = __expf(s[nt][2] - mnew[1]);
            float p3 = __expf(s[nt][3] - mnew[1]);
            rs0 += p0 + p1;
            rs1 += p2 + p3;
            plo[nt] = pack_h2(p0, p1);
            phi[nt] = pack_h2(p2, p3);
        }
        lrun[0] = lrun[0] * ci[0] + rs0;
        lrun[1] = lrun[1] * ci[1] + rs1;
#pragma unroll
        for (int nt = 0; nt < 16; nt++) {
            o[nt][0] *= ci[0];
            o[nt][1] *= ci[0];
            o[nt][2] *= ci[1];
            o[nt][3] *= ci[1];
        }

        // ---- O += P @ V (fp16), V as B via ldmatrix.trans --------------------
#pragma unroll
        for (int kk2 = 0; kk2 < 4; kk2++) {
            uint32_t a[4] = {plo[2 * kk2], phi[2 * kk2],
                             plo[2 * kk2 + 1], phi[2 * kk2 + 1]};
            uint32_t kvr = kk2 * 16 + (lane & 7) + (((lane >> 3) & 1) << 3);
#pragma unroll
            for (int dt = 0; dt < 8; dt++) {
                uint32_t dcol = dt * 16 + ((lane >> 4) << 3);
                uint32_t off = (uint32_t)(dcol >> 6) * 8192 +
                               sw128(kvr * 128 + (dcol & 63) * 2);
                uint32_t bv4[4];
                ldsm4t(kb + 32768 + off, bv4);
                mma16816h(o[dt * 2],     a, &bv4[0]);
                mma16816h(o[dt * 2 + 1], a, &bv4[2]);
            }
        }
        // no trailing sync: top-of-loop sync protects buffer reuse
    }

    // ---- finalize l across the quad, normalize, store ------------------------
#pragma unroll
    for (int off = 1; off <= 2; off <<= 1) {
        lrun[0] += __shfl_xor_sync(0xffffffffu, lrun[0], off);
        lrun[1] += __shfl_xor_sync(0xffffffffu, lrun[1], off);
    }
    const float inv0 = 1.0f / lrun[0];
    const float inv1 = 1.0f / lrun[1];
    const int row0 = qt * 128 + w * 16 + (lane >> 2);
    const size_t ob = ((size_t)(b * Nv + n) * Sv) * Dv;
#pragma unroll
    for (int nt = 0; nt < 16; nt++) {
        int d = nt * 8 + (lane & 3) * 2;
        *(float2*)&out[ob + (size_t)row0 * Dv + d] =
            make_float2(o[nt][0] * inv0, o[nt][1] * inv0);
        *(float2*)&out[ob + (size_t)(row0 + 8) * Dv + d] =
            make_float2(o[nt][2] * inv1, o[nt][3] * inv1);
    }
}

// ---------------------------------------------------------------------------
extern "C" void kernel_launch(void* const* d_in, const int* in_sizes, int n_in,
                              void* d_out, int out_size)
{
    const float* hs = (const float*)d_in[0];
    const float* Wq = (const float*)d_in[1];
    const float* bq = (const float*)d_in[2];
    const float* Wk = (const float*)d_in[3];
    const float* bk = (const float*)d_in[4];
    const float* Wv = (const float*)d_in[5];
    const float* bv = (const float*)d_in[6];
    float* out = (float*)d_out;

    conv_a_kernel<<<(Bv * Sv * Hv / 4) / 256, 256>>>(hs);
    conv_b_kernel<<<dim3(NCOL / 32, Hv / 32), dim3(32, 8)>>>(Wq, Wk, Wv);

    const int proj_smem = 2 * PSTAGE;
    cudaFuncSetAttribute(proj_mma_kernel,
                         cudaFuncAttributeMaxDynamicSharedMemorySize, proj_smem);
    proj_mma_kernel<<<dim3(32, 18), 256, proj_smem>>>(bq, bk, bv);

    const int attn_smem = 4 * KV_STAGE;   // 192 KB (Q prologue reuses stage 0/1)
    cudaFuncSetAttribute(attn_mma_kernel,
                         cudaFuncAttributeMaxDynamicSharedMemorySize, attn_smem);
    dim3 ga(Sv / 128, Nv, Bv);
    attn_mma_kernel<<<ga, 256, attn_smem>>>(out);
}